// round 15
// baseline (speedup 1.0000x reference)
#include <cuda_runtime.h>
#include <stdint.h>

#define BB 32
#define AA 65536
#define CC 21
#define NANCH (BB*AA)
#define MAIN_BLOCKS (NANCH/256)
#define CNT_STRIDE 32            // pad per-row counters to separate cache lines

// ---------------- scratch (device globals; no allocation allowed) ----------
__device__ float        g_cand[NANCH];        // compacted nonzero neg CEs per row
__device__ unsigned int g_cnt[BB*CNT_STRIDE]; // per-row nonzero count (padded)
__device__ int          g_numpos[BB];
__device__ double       g_rowneg[BB];         // per-row total nonzero-neg sum
__device__ double       g_locsum;
__device__ double       g_posce;
__device__ double       g_negsum;
__device__ int          g_tp;                 // total positives across batch
__device__ unsigned int g_done;

// ---------------- helpers ---------------------------------------------------
// Reduce three doubles across a 256-thread block. Results valid on tid 0.
__device__ __forceinline__ void blockReduce3(double& x, double& y, double& z,
                                             double* sred /* >= 24 doubles */) {
    int lane = threadIdx.x & 31, wid = threadIdx.x >> 5;
#pragma unroll
    for (int o = 16; o; o >>= 1) {
        x += __shfl_down_sync(0xffffffffu, x, o);
        y += __shfl_down_sync(0xffffffffu, y, o);
        z += __shfl_down_sync(0xffffffffu, z, o);
    }
    if (lane == 0) { sred[wid*3] = x; sred[wid*3+1] = y; sred[wid*3+2] = z; }
    __syncthreads();
    if (wid == 0) {
        double a = (lane < 8) ? sred[lane*3]   : 0.0;
        double b = (lane < 8) ? sred[lane*3+1] : 0.0;
        double c = (lane < 8) ? sred[lane*3+2] : 0.0;
#pragma unroll
        for (int o = 4; o; o >>= 1) {
            a += __shfl_down_sync(0xffffffffu, a, o);
            b += __shfl_down_sync(0xffffffffu, b, o);
            c += __shfl_down_sync(0xffffffffu, c, o);
        }
        x = a; y = b; z = c;
    }
}

struct DigitSmem {
    unsigned sS[256];
    unsigned sc[256];
    unsigned swm[8];
    unsigned sdig;
};

// Block-parallel (256 threads) digit finder over a 256-bin shared histogram.
__device__ __forceinline__ unsigned find_digit(const unsigned* __restrict__ hist,
                                               long long& krem, DigitSmem* ds) {
    const int tid = threadIdx.x, lane = tid & 31, w = tid >> 5;
    unsigned c = hist[tid];
    unsigned S = c;
#pragma unroll
    for (int off = 1; off < 32; off <<= 1) {
        unsigned t = __shfl_down_sync(0xffffffffu, S, off);
        if (lane + off < 32) S += t;
    }
    if (lane == 0) ds->swm[w] = S;
    __syncthreads();
    unsigned add = 0;
#pragma unroll
    for (int ww = 0; ww < 8; ww++) if (ww > w) add += ds->swm[ww];
    S += add;
    ds->sS[tid] = S;
    ds->sc[tid] = c;
    __syncthreads();
    bool p = ((long long)S >= krem);
    unsigned bal = __ballot_sync(0xffffffffu, p);
    __syncthreads();
    if (lane == 0) ds->swm[w] = bal;
    __syncthreads();
    if (tid == 0) {
        int dig = 0;
#pragma unroll
        for (int ww = 7; ww >= 0; --ww) {
            if (ds->swm[ww]) { dig = ww * 32 + (31 - __clz(ds->swm[ww])); break; }
        }
        ds->sdig = (unsigned)dig;
    }
    __syncthreads();
    unsigned d = ds->sdig;
    krem -= (long long)ds->sS[d] - (long long)ds->sc[d];
    return d;
}

// ---------------- main kernel ------------------------------------------------
__global__ void __launch_bounds__(256) main_k(const float* __restrict__ locp,
                                              const float* __restrict__ loct,
                                              const float* __restrict__ cls,
                                              const int* __restrict__ tgt) {
    __shared__ float  scls[256*CC];
    __shared__ double sred[24];

    const int tid    = threadIdx.x;
    const int lane   = tid & 31;
    const int anchor = blockIdx.x * 256 + tid;
    const int row    = anchor >> 16;          // uniform per block

    // stage cls tile (coalesced float4)
    {
        const float4* src = reinterpret_cast<const float4*>(cls) + (size_t)blockIdx.x * (256*CC/4);
        float4*       dst = reinterpret_cast<float4*>(scls);
#pragma unroll
        for (int i = 0; i < 6; i++) {
            int idx = tid + i * 256;
            if (idx < 256*CC/4) dst[idx] = src[idx];
        }
    }
    __syncthreads();

    int  t   = tgt[anchor];
    bool pos = (t > 0);

    // logsumexp over 21 classes (stride-21 LDS is bank-conflict-free)
    float v[CC];
#pragma unroll
    for (int c = 0; c < CC; c++) v[c] = scls[tid*CC + c];
    float m = v[0];
#pragma unroll
    for (int c = 1; c < CC; c++) m = fmaxf(m, v[c]);
    float s = 0.f;
#pragma unroll
    for (int c = 0; c < CC; c++) s += __expf(v[c] - m);

    int tc = t; tc = tc < 0 ? 0 : (tc > CC-1 ? CC-1 : tc);
    float picked = scls[tid*CC + tc];
    float ce     = (t == -1) ? 0.f : (m + __logf(s) - picked);
    float negc   = pos ? 0.f : ce;

    // compact nonzero negatives (warp-aggregated)
    {
        unsigned bits = __float_as_uint(negc);
        unsigned mkz  = __ballot_sync(0xffffffffu, bits != 0u);
        if (mkz) {
            int leader = __ffs(mkz) - 1;
            unsigned base = 0;
            if (lane == leader) base = atomicAdd(&g_cnt[row*CNT_STRIDE], (unsigned)__popc(mkz));
            base = __shfl_sync(0xffffffffu, base, leader);
            if (bits != 0u) {
                unsigned off = (unsigned)__popc(mkz & ((1u << lane) - 1u));
                g_cand[(size_t)row*AA + base + off] = negc;
            }
        }
    }

    // smooth-L1 (unconditional loads; masked result)
    float4 p = reinterpret_cast<const float4*>(locp)[anchor];
    float4 q = reinterpret_cast<const float4*>(loct)[anchor];
    float d0 = p.x-q.x, d1 = p.y-q.y, d2 = p.z-q.z, d3 = p.w-q.w;
    float a0 = fabsf(d0), a1 = fabsf(d1), a2 = fabsf(d2), a3 = fabsf(d3);
    float lsum = (a0 < 1.f ? 0.5f*d0*d0 : a0-0.5f)
               + (a1 < 1.f ? 0.5f*d1*d1 : a1-0.5f)
               + (a2 < 1.f ? 0.5f*d2*d2 : a2-0.5f)
               + (a3 < 1.f ? 0.5f*d3*d3 : a3-0.5f);
    if (!pos) lsum = 0.f;

    int npos = __syncthreads_count(pos ? 1 : 0);

    double bl = (double)lsum;
    double bp = pos ? (double)ce : 0.0;
    double bn = (double)negc;
    blockReduce3(bl, bp, bn, sred);

    if (tid == 0) {
        atomicAdd(&g_locsum, bl);
        atomicAdd(&g_posce,  bp);
        atomicAdd(&g_rowneg[row], bn);
        atomicAdd(&g_numpos[row], npos);
    }
}

// ---------------- tiny per-row select (fast path reads 3 scalars) ------------
__global__ void __launch_bounds__(256) select_k(float* __restrict__ out) {
    __shared__ DigitSmem ds;
    __shared__ unsigned  shist[256];
    __shared__ double    sred[24];
    __shared__ int       s_last;

    const int row = blockIdx.x;
    const int tid = threadIdx.x;

    const int n    = (int)g_cnt[row*CNT_STRIDE];
    const int npos = g_numpos[row];
    long long k = 3LL * (long long)npos;
    if (k < 1) k = 1;
    if (k > AA-1) k = AA-1;

    double negrow;
    if (k >= (long long)n) {
        negrow = g_rowneg[row];           // all nonzeros selected; ties are zeros
    } else {
        const float* cand = g_cand + (size_t)row*AA;
        // level-0 histogram
        shist[tid] = 0u;
        __syncthreads();
        for (int i = tid; i < n; i += 256)
            atomicAdd(&shist[__float_as_uint(cand[i]) >> 24], 1u);
        __syncthreads();
        long long krem = k;
        unsigned pfx = find_digit(shist, krem, &ds);
        // levels 1..3
#pragma unroll
        for (int shift = 16; shift >= 0; shift -= 8) {
            __syncthreads();
            shist[tid] = 0u;
            __syncthreads();
            for (int i = tid; i < n; i += 256) {
                unsigned b = __float_as_uint(cand[i]);
                if ((b >> (shift + 8)) == pfx)
                    atomicAdd(&shist[(b >> shift) & 255u], 1u);
            }
            __syncthreads();
            pfx = (pfx << 8) | find_digit(shist, krem, &ds);
        }
        const unsigned tb = pfx;
        double sgt = 0.0, d1 = 0.0, d2 = 0.0;
        for (int i = tid; i < n; i += 256) {
            unsigned b = __float_as_uint(cand[i]);
            if (b > tb) sgt += (double)__uint_as_float(b);
        }
        __syncthreads();
        blockReduce3(sgt, d1, d2, sred);
        negrow = sgt + (double)krem * (double)__uint_as_float(tb);
    }

    // per-row state reset for next graph replay
    if (tid == 0) {
        g_cnt[row*CNT_STRIDE] = 0u;
        g_numpos[row] = 0;
        g_rowneg[row] = 0.0;
        atomicAdd(&g_negsum, negrow);
        atomicAdd(&g_tp, npos);
        __threadfence();
        unsigned ticket = atomicAdd(&g_done, 1u);
        s_last = (ticket == BB - 1) ? 1 : 0;
    }
    __syncthreads();

    if (s_last && tid == 0) {
        __threadfence();
        double tp = (double)g_tp;
        out[0] = (float)(20.0 * g_locsum / tp);
        out[1] = (float)((g_posce + g_negsum) / tp);
        g_locsum = 0.0;
        g_posce  = 0.0;
        g_negsum = 0.0;
        g_tp     = 0;
        __threadfence();
        g_done   = 0u;
    }
}

// ---------------- launch -----------------------------------------------------
extern "C" void kernel_launch(void* const* d_in, const int* in_sizes, int n_in,
                              void* d_out, int out_size) {
    const float* locp = (const float*)d_in[0];
    const float* loct = (const float*)d_in[1];
    const float* cls  = (const float*)d_in[2];
    const int*   tgt  = (const int*)d_in[3];
    float* out = (float*)d_out;

    main_k<<<MAIN_BLOCKS, 256>>>(locp, loct, cls, tgt);
    select_k<<<BB, 256>>>(out);
}

// round 16
// speedup vs baseline: 1.3553x; 1.3553x over previous
#include <cuda_runtime.h>
#include <stdint.h>

#define BB 32
#define AA 65536
#define CC 21
#define NANCH (BB*AA)
#define MAIN_BLOCKS (NANCH/256)
#define CNT_STRIDE 32            // pad per-row counters to separate cache lines

// ---------------- scratch (device globals; no allocation allowed) ----------
__device__ float        g_cand[NANCH];        // compacted nonzero neg CEs per row
__device__ unsigned int g_cnt[BB*CNT_STRIDE]; // per-row nonzero count (padded)
__device__ int          g_numpos[BB];
__device__ double       g_rowneg[BB];         // per-row total nonzero-neg sum
__device__ double       g_locsum;
__device__ double       g_posce;
__device__ double       g_negsum;
__device__ int          g_tp;                 // total positives across batch
__device__ unsigned int g_done;

// ---------------- helpers ---------------------------------------------------
// Reduce two doubles at once across a 256-thread block. Results valid on tid 0.
__device__ __forceinline__ void blockReduce2(double& x, double& y, double2* sred) {
    int lane = threadIdx.x & 31, wid = threadIdx.x >> 5;
#pragma unroll
    for (int o = 16; o; o >>= 1) {
        x += __shfl_down_sync(0xffffffffu, x, o);
        y += __shfl_down_sync(0xffffffffu, y, o);
    }
    if (lane == 0) sred[wid] = make_double2(x, y);
    __syncthreads();
    if (wid == 0) {
        double2 r = (lane < 8) ? sred[lane] : make_double2(0.0, 0.0);
        double a = r.x, b = r.y;
#pragma unroll
        for (int o = 4; o; o >>= 1) {
            a += __shfl_down_sync(0xffffffffu, a, o);
            b += __shfl_down_sync(0xffffffffu, b, o);
        }
        x = a; y = b;
    }
}

struct DigitSmem {
    unsigned sS[256];
    unsigned sc[256];
    unsigned swm[8];
    unsigned sdig;
};

// Block-parallel (256 threads) digit finder over a 256-bin shared histogram.
__device__ __forceinline__ unsigned find_digit(const unsigned* __restrict__ hist,
                                               long long& krem, DigitSmem* ds) {
    const int tid = threadIdx.x, lane = tid & 31, w = tid >> 5;
    unsigned c = hist[tid];
    unsigned S = c;
#pragma unroll
    for (int off = 1; off < 32; off <<= 1) {
        unsigned t = __shfl_down_sync(0xffffffffu, S, off);
        if (lane + off < 32) S += t;
    }
    if (lane == 0) ds->swm[w] = S;
    __syncthreads();
    unsigned add = 0;
#pragma unroll
    for (int ww = 0; ww < 8; ww++) if (ww > w) add += ds->swm[ww];
    S += add;
    ds->sS[tid] = S;
    ds->sc[tid] = c;
    __syncthreads();
    bool p = ((long long)S >= krem);
    unsigned bal = __ballot_sync(0xffffffffu, p);
    __syncthreads();
    if (lane == 0) ds->swm[w] = bal;
    __syncthreads();
    if (tid == 0) {
        int dig = 0;
#pragma unroll
        for (int ww = 7; ww >= 0; --ww) {
            if (ds->swm[ww]) { dig = ww * 32 + (31 - __clz(ds->swm[ww])); break; }
        }
        ds->sdig = (unsigned)dig;
    }
    __syncthreads();
    unsigned d = ds->sdig;
    krem -= (long long)ds->sS[d] - (long long)ds->sc[d];
    return d;
}

// ---------------- main kernel ------------------------------------------------
__global__ void __launch_bounds__(256) main_k(const float* __restrict__ locp,
                                              const float* __restrict__ loct,
                                              const float* __restrict__ cls,
                                              const int* __restrict__ tgt) {
    __shared__ float   scls[256*CC];
    __shared__ double2 sred[8];
    __shared__ float   s_negs;      // sparse per-block nonzero-neg accumulator

    const int tid    = threadIdx.x;
    const int lane   = tid & 31;
    const int anchor = blockIdx.x * 256 + tid;
    const int row    = anchor >> 16;          // uniform per block

    if (tid == 0) s_negs = 0.f;

    // stage cls tile (coalesced float4)
    {
        const float4* src = reinterpret_cast<const float4*>(cls) + (size_t)blockIdx.x * (256*CC/4);
        float4*       dst = reinterpret_cast<float4*>(scls);
#pragma unroll
        for (int i = 0; i < 6; i++) {
            int idx = tid + i * 256;
            if (idx < 256*CC/4) dst[idx] = src[idx];
        }
    }
    __syncthreads();

    int  t   = tgt[anchor];
    bool pos = (t > 0);

    // logsumexp over 21 classes (stride-21 LDS is bank-conflict-free)
    float v[CC];
#pragma unroll
    for (int c = 0; c < CC; c++) v[c] = scls[tid*CC + c];
    float m = v[0];
#pragma unroll
    for (int c = 1; c < CC; c++) m = fmaxf(m, v[c]);
    float s = 0.f;
#pragma unroll
    for (int c = 0; c < CC; c++) s += __expf(v[c] - m);

    int tc = t; tc = tc < 0 ? 0 : (tc > CC-1 ? CC-1 : tc);
    float picked = scls[tid*CC + tc];
    float ce     = (t == -1) ? 0.f : (m + __logf(s) - picked);
    float negc   = pos ? 0.f : ce;

    // compact nonzero negatives (warp-aggregated) + sparse rowneg accumulation
    {
        unsigned bits = __float_as_uint(negc);
        unsigned mkz  = __ballot_sync(0xffffffffu, bits != 0u);
        if (mkz) {
            int leader = __ffs(mkz) - 1;
            unsigned base = 0;
            if (lane == leader) base = atomicAdd(&g_cnt[row*CNT_STRIDE], (unsigned)__popc(mkz));
            base = __shfl_sync(0xffffffffu, base, leader);
            if (bits != 0u) {
                unsigned off = (unsigned)__popc(mkz & ((1u << lane) - 1u));
                g_cand[(size_t)row*AA + base + off] = negc;
                atomicAdd(&s_negs, negc);          // ~12 per block; off critical path
            }
        }
    }

    // smooth-L1 (unconditional loads; masked result)
    float4 p = reinterpret_cast<const float4*>(locp)[anchor];
    float4 q = reinterpret_cast<const float4*>(loct)[anchor];
    float d0 = p.x-q.x, d1 = p.y-q.y, d2 = p.z-q.z, d3 = p.w-q.w;
    float a0 = fabsf(d0), a1 = fabsf(d1), a2 = fabsf(d2), a3 = fabsf(d3);
    float lsum = (a0 < 1.f ? 0.5f*d0*d0 : a0-0.5f)
               + (a1 < 1.f ? 0.5f*d1*d1 : a1-0.5f)
               + (a2 < 1.f ? 0.5f*d2*d2 : a2-0.5f)
               + (a3 < 1.f ? 0.5f*d3*d3 : a3-0.5f);
    if (!pos) lsum = 0.f;

    int npos = __syncthreads_count(pos ? 1 : 0);   // drains s_negs atomics too

    double bl = (double)lsum;
    double bp = pos ? (double)ce : 0.0;
    blockReduce2(bl, bp, sred);

    if (tid == 0) {
        atomicAdd(&g_locsum, bl);
        atomicAdd(&g_posce,  bp);
        atomicAdd(&g_numpos[row], npos);
        atomicAdd(&g_rowneg[row], (double)s_negs);
    }
}

// ---------------- tiny per-row select (fast path reads 3 scalars) ------------
__global__ void __launch_bounds__(256) select_k(float* __restrict__ out) {
    __shared__ DigitSmem ds;
    __shared__ unsigned  shist[256];
    __shared__ double2   sred[8];
    __shared__ int       s_last;

    const int row = blockIdx.x;
    const int tid = threadIdx.x;

    const int n    = (int)g_cnt[row*CNT_STRIDE];
    const int npos = g_numpos[row];
    long long k = 3LL * (long long)npos;
    if (k < 1) k = 1;
    if (k > AA-1) k = AA-1;

    double negrow;
    if (k >= (long long)n) {
        negrow = g_rowneg[row];           // all nonzeros selected; ties are zeros
    } else {
        const float* cand = g_cand + (size_t)row*AA;
        // level-0 histogram
        shist[tid] = 0u;
        __syncthreads();
        for (int i = tid; i < n; i += 256)
            atomicAdd(&shist[__float_as_uint(cand[i]) >> 24], 1u);
        __syncthreads();
        long long krem = k;
        unsigned pfx = find_digit(shist, krem, &ds);
        // levels 1..3
#pragma unroll
        for (int shift = 16; shift >= 0; shift -= 8) {
            __syncthreads();
            shist[tid] = 0u;
            __syncthreads();
            for (int i = tid; i < n; i += 256) {
                unsigned b = __float_as_uint(cand[i]);
                if ((b >> (shift + 8)) == pfx)
                    atomicAdd(&shist[(b >> shift) & 255u], 1u);
            }
            __syncthreads();
            pfx = (pfx << 8) | find_digit(shist, krem, &ds);
        }
        const unsigned tb = pfx;
        double sgt = 0.0, dummy = 0.0;
        for (int i = tid; i < n; i += 256) {
            unsigned b = __float_as_uint(cand[i]);
            if (b > tb) sgt += (double)__uint_as_float(b);
        }
        __syncthreads();
        blockReduce2(sgt, dummy, sred);
        negrow = sgt + (double)krem * (double)__uint_as_float(tb);
    }

    // per-row state reset for next graph replay
    if (tid == 0) {
        g_cnt[row*CNT_STRIDE] = 0u;
        g_numpos[row] = 0;
        g_rowneg[row] = 0.0;
        atomicAdd(&g_negsum, negrow);
        atomicAdd(&g_tp, npos);
        __threadfence();
        unsigned ticket = atomicAdd(&g_done, 1u);
        s_last = (ticket == BB - 1) ? 1 : 0;
    }
    __syncthreads();

    if (s_last && tid == 0) {
        __threadfence();
        double tp = (double)g_tp;
        out[0] = (float)(20.0 * g_locsum / tp);
        out[1] = (float)((g_posce + g_negsum) / tp);
        g_locsum = 0.0;
        g_posce  = 0.0;
        g_negsum = 0.0;
        g_tp     = 0;
        __threadfence();
        g_done   = 0u;
    }
}

// ---------------- launch -----------------------------------------------------
extern "C" void kernel_launch(void* const* d_in, const int* in_sizes, int n_in,
                              void* d_out, int out_size) {
    const float* locp = (const float*)d_in[0];
    const float* loct = (const float*)d_in[1];
    const float* cls  = (const float*)d_in[2];
    const int*   tgt  = (const int*)d_in[3];
    float* out = (float*)d_out;

    main_k<<<MAIN_BLOCKS, 256>>>(locp, loct, cls, tgt);
    select_k<<<BB, 256>>>(out);
}

// round 17
// speedup vs baseline: 1.7377x; 1.2821x over previous
#include <cuda_runtime.h>
#include <stdint.h>

#define BB 32
#define AA 65536
#define CC 21
#define NANCH (BB*AA)
#define MAIN_BLOCKS (NANCH/256)
#define CNT_STRIDE 32            // pad per-row counters to separate cache lines

// ---------------- scratch (device globals; no allocation allowed) ----------
__device__ float        g_cand[NANCH];        // compacted nonzero neg CEs per row
__device__ unsigned int g_cnt[BB*CNT_STRIDE]; // per-row nonzero count (padded)
__device__ int          g_numpos[BB];
__device__ double       g_rowneg[BB];         // per-row total nonzero-neg sum
__device__ double       g_locsum;
__device__ double       g_posce;
__device__ double       g_negsum;
__device__ int          g_tp;                 // total positives across batch
__device__ unsigned int g_done;

// ---------------- helpers ---------------------------------------------------
// Reduce two doubles at once across a 256-thread block. Results valid on tid 0.
// (used only by select_k's rare slow path)
__device__ __forceinline__ void blockReduce2(double& x, double& y, double2* sred) {
    int lane = threadIdx.x & 31, wid = threadIdx.x >> 5;
#pragma unroll
    for (int o = 16; o; o >>= 1) {
        x += __shfl_down_sync(0xffffffffu, x, o);
        y += __shfl_down_sync(0xffffffffu, y, o);
    }
    if (lane == 0) sred[wid] = make_double2(x, y);
    __syncthreads();
    if (wid == 0) {
        double2 r = (lane < 8) ? sred[lane] : make_double2(0.0, 0.0);
        double a = r.x, b = r.y;
#pragma unroll
        for (int o = 4; o; o >>= 1) {
            a += __shfl_down_sync(0xffffffffu, a, o);
            b += __shfl_down_sync(0xffffffffu, b, o);
        }
        x = a; y = b;
    }
}

struct DigitSmem {
    unsigned sS[256];
    unsigned sc[256];
    unsigned swm[8];
    unsigned sdig;
};

// Block-parallel (256 threads) digit finder over a 256-bin shared histogram.
__device__ __forceinline__ unsigned find_digit(const unsigned* __restrict__ hist,
                                               long long& krem, DigitSmem* ds) {
    const int tid = threadIdx.x, lane = tid & 31, w = tid >> 5;
    unsigned c = hist[tid];
    unsigned S = c;
#pragma unroll
    for (int off = 1; off < 32; off <<= 1) {
        unsigned t = __shfl_down_sync(0xffffffffu, S, off);
        if (lane + off < 32) S += t;
    }
    if (lane == 0) ds->swm[w] = S;
    __syncthreads();
    unsigned add = 0;
#pragma unroll
    for (int ww = 0; ww < 8; ww++) if (ww > w) add += ds->swm[ww];
    S += add;
    ds->sS[tid] = S;
    ds->sc[tid] = c;
    __syncthreads();
    bool p = ((long long)S >= krem);
    unsigned bal = __ballot_sync(0xffffffffu, p);
    __syncthreads();
    if (lane == 0) ds->swm[w] = bal;
    __syncthreads();
    if (tid == 0) {
        int dig = 0;
#pragma unroll
        for (int ww = 7; ww >= 0; --ww) {
            if (ds->swm[ww]) { dig = ww * 32 + (31 - __clz(ds->swm[ww])); break; }
        }
        ds->sdig = (unsigned)dig;
    }
    __syncthreads();
    unsigned d = ds->sdig;
    krem -= (long long)ds->sS[d] - (long long)ds->sc[d];
    return d;
}

// ---------------- main kernel ------------------------------------------------
__global__ void __launch_bounds__(256) main_k(const float* __restrict__ locp,
                                              const float* __restrict__ loct,
                                              const float* __restrict__ cls,
                                              const int* __restrict__ tgt) {
    __shared__ float scls[256*CC];
    __shared__ float s_negs;        // sparse per-block nonzero-neg accumulator
    __shared__ float s_loc;         // per-block smooth-L1 sum (float)
    __shared__ float s_ce;          // per-block positive-CE sum (float)

    const int tid    = threadIdx.x;
    const int lane   = tid & 31;
    const int anchor = blockIdx.x * 256 + tid;
    const int row    = anchor >> 16;          // uniform per block

    if (tid == 0) { s_negs = 0.f; s_loc = 0.f; s_ce = 0.f; }

    // stage cls tile (coalesced float4)
    {
        const float4* src = reinterpret_cast<const float4*>(cls) + (size_t)blockIdx.x * (256*CC/4);
        float4*       dst = reinterpret_cast<float4*>(scls);
#pragma unroll
        for (int i = 0; i < 6; i++) {
            int idx = tid + i * 256;
            if (idx < 256*CC/4) dst[idx] = src[idx];
        }
    }
    __syncthreads();                           // also orders s_* init

    int  t   = tgt[anchor];
    bool pos = (t > 0);

    // logsumexp over 21 classes (stride-21 LDS is bank-conflict-free)
    float v[CC];
#pragma unroll
    for (int c = 0; c < CC; c++) v[c] = scls[tid*CC + c];
    float m = v[0];
#pragma unroll
    for (int c = 1; c < CC; c++) m = fmaxf(m, v[c]);
    float s = 0.f;
#pragma unroll
    for (int c = 0; c < CC; c++) s += __expf(v[c] - m);

    int tc = t; tc = tc < 0 ? 0 : (tc > CC-1 ? CC-1 : tc);
    float picked = scls[tid*CC + tc];
    float ce     = (t == -1) ? 0.f : (m + __logf(s) - picked);
    float negc   = pos ? 0.f : ce;

    // compact nonzero negatives (warp-aggregated) + sparse rowneg accumulation
    {
        unsigned bits = __float_as_uint(negc);
        unsigned mkz  = __ballot_sync(0xffffffffu, bits != 0u);
        if (mkz) {
            int leader = __ffs(mkz) - 1;
            unsigned base = 0;
            if (lane == leader) base = atomicAdd(&g_cnt[row*CNT_STRIDE], (unsigned)__popc(mkz));
            base = __shfl_sync(0xffffffffu, base, leader);
            if (bits != 0u) {
                unsigned off = (unsigned)__popc(mkz & ((1u << lane) - 1u));
                g_cand[(size_t)row*AA + base + off] = negc;
                atomicAdd(&s_negs, negc);          // ~12 per block; off critical path
            }
        }
    }

    // smooth-L1 (unconditional loads; masked result)
    float4 p = reinterpret_cast<const float4*>(locp)[anchor];
    float4 q = reinterpret_cast<const float4*>(loct)[anchor];
    float d0 = p.x-q.x, d1 = p.y-q.y, d2 = p.z-q.z, d3 = p.w-q.w;
    float a0 = fabsf(d0), a1 = fabsf(d1), a2 = fabsf(d2), a3 = fabsf(d3);
    float lsum = (a0 < 1.f ? 0.5f*d0*d0 : a0-0.5f)
               + (a1 < 1.f ? 0.5f*d1*d1 : a1-0.5f)
               + (a2 < 1.f ? 0.5f*d2*d2 : a2-0.5f)
               + (a3 < 1.f ? 0.5f*d3*d3 : a3-0.5f);
    if (!pos) lsum = 0.f;

    // float warp reduce (one phase, 10 SHFL.32) + per-warp shared atomics
    float fl = lsum;
    float fp = pos ? ce : 0.f;
#pragma unroll
    for (int o = 16; o; o >>= 1) {
        fl += __shfl_down_sync(0xffffffffu, fl, o);
        fp += __shfl_down_sync(0xffffffffu, fp, o);
    }
    if (lane == 0) {
        atomicAdd(&s_loc, fl);
        atomicAdd(&s_ce,  fp);
    }

    int npos = __syncthreads_count(pos ? 1 : 0);   // drains all shared atomics

    if (tid == 0) {
        atomicAdd(&g_locsum, (double)s_loc);
        atomicAdd(&g_posce,  (double)s_ce);
        atomicAdd(&g_numpos[row], npos);
        atomicAdd(&g_rowneg[row], (double)s_negs);
    }
}

// ---------------- tiny per-row select (fast path reads 3 scalars) ------------
__global__ void __launch_bounds__(256) select_k(float* __restrict__ out) {
    __shared__ DigitSmem ds;
    __shared__ unsigned  shist[256];
    __shared__ double2   sred[8];
    __shared__ int       s_last;

    const int row = blockIdx.x;
    const int tid = threadIdx.x;

    const int n    = (int)g_cnt[row*CNT_STRIDE];
    const int npos = g_numpos[row];
    long long k = 3LL * (long long)npos;
    if (k < 1) k = 1;
    if (k > AA-1) k = AA-1;

    double negrow;
    if (k >= (long long)n) {
        negrow = g_rowneg[row];           // all nonzeros selected; ties are zeros
    } else {
        const float* cand = g_cand + (size_t)row*AA;
        // level-0 histogram
        shist[tid] = 0u;
        __syncthreads();
        for (int i = tid; i < n; i += 256)
            atomicAdd(&shist[__float_as_uint(cand[i]) >> 24], 1u);
        __syncthreads();
        long long krem = k;
        unsigned pfx = find_digit(shist, krem, &ds);
        // levels 1..3
#pragma unroll
        for (int shift = 16; shift >= 0; shift -= 8) {
            __syncthreads();
            shist[tid] = 0u;
            __syncthreads();
            for (int i = tid; i < n; i += 256) {
                unsigned b = __float_as_uint(cand[i]);
                if ((b >> (shift + 8)) == pfx)
                    atomicAdd(&shist[(b >> shift) & 255u], 1u);
            }
            __syncthreads();
            pfx = (pfx << 8) | find_digit(shist, krem, &ds);
        }
        const unsigned tb = pfx;
        double sgt = 0.0, dummy = 0.0;
        for (int i = tid; i < n; i += 256) {
            unsigned b = __float_as_uint(cand[i]);
            if (b > tb) sgt += (double)__uint_as_float(b);
        }
        __syncthreads();
        blockReduce2(sgt, dummy, sred);
        negrow = sgt + (double)krem * (double)__uint_as_float(tb);
    }

    // per-row state reset for next graph replay
    if (tid == 0) {
        g_cnt[row*CNT_STRIDE] = 0u;
        g_numpos[row] = 0;
        g_rowneg[row] = 0.0;
        atomicAdd(&g_negsum, negrow);
        atomicAdd(&g_tp, npos);
        __threadfence();
        unsigned ticket = atomicAdd(&g_done, 1u);
        s_last = (ticket == BB - 1) ? 1 : 0;
    }
    __syncthreads();

    if (s_last && tid == 0) {
        __threadfence();
        double tp = (double)g_tp;
        out[0] = (float)(20.0 * g_locsum / tp);
        out[1] = (float)((g_posce + g_negsum) / tp);
        g_locsum = 0.0;
        g_posce  = 0.0;
        g_negsum = 0.0;
        g_tp     = 0;
        __threadfence();
        g_done   = 0u;
    }
}

// ---------------- launch -----------------------------------------------------
extern "C" void kernel_launch(void* const* d_in, const int* in_sizes, int n_in,
                              void* d_out, int out_size) {
    const float* locp = (const float*)d_in[0];
    const float* loct = (const float*)d_in[1];
    const float* cls  = (const float*)d_in[2];
    const int*   tgt  = (const int*)d_in[3];
    float* out = (float*)d_out;

    main_k<<<MAIN_BLOCKS, 256>>>(locp, loct, cls, tgt);
    select_k<<<BB, 256>>>(out);
}